// round 4
// baseline (speedup 1.0000x reference)
#include <cuda_runtime.h>
#include <math.h>

#define Nn 10000
#define Ne 160000

// ---------------- scratch (device globals; no allocation allowed) ----------
__device__ float g_s_up [Nn*64];
__device__ float g_v_up [Nn*192];        // [n][c*3+i]
__device__ float g_skip_s[Nn*128];
__device__ float g_skip_v[Nn*192];       // [n][c*3+i]
__device__ float g_agg_s[Nn*128];
__device__ float g_agg_v[Nn*576];        // [n][i][o] : i<3, o<192
__device__ float g_mix  [(size_t)Ne*320];

__device__ __forceinline__ float sw(float x){ return x/(1.f+__expf(-x)); }

__device__ __forceinline__ void red4(float* p, float a, float b, float c, float d){
    asm volatile("red.global.add.v4.f32 [%0], {%1,%2,%3,%4};"
                 :: "l"(p), "f"(a), "f"(b), "f"(c), "f"(d) : "memory");
}

// ---- packed f32x2 helpers (sm_100+) ----
typedef unsigned long long u64t;
__device__ __forceinline__ u64t pk(float lo, float hi){
    u64t r; asm("mov.b64 %0, {%1,%2};" : "=l"(r) : "f"(lo), "f"(hi)); return r;
}
__device__ __forceinline__ void fma2(u64t &d, u64t a, u64t b){
    asm("fma.rn.f32x2 %0, %1, %2, %0;" : "+l"(d) : "l"(a), "l"(b));
}
__device__ __forceinline__ float2 up2(u64t v){
    float2 r; asm("mov.b64 {%0,%1}, %2;" : "=f"(r.x), "=f"(r.y) : "l"(v)); return r;
}

// ---------------- K1: node prep (s_up, v_up, skip_s, skip_v) ---------------
__global__ __launch_bounds__(256) void k_node_prep(
    const float* __restrict__ ns, const float* __restrict__ nv,
    const int*   __restrict__ spec,
    const float* __restrict__ Wss, const float* __restrict__ Wsv,
    const float* __restrict__ Wus, const float* __restrict__ Wuv)
{
    __shared__ float sWus[4096], sWuv[4096];
    __shared__ float stage[8][256];
    int tid = threadIdx.x;
    for(int i=tid;i<4096;i+=256){ sWus[i]=Wus[i]; sWuv[i]=Wuv[i]; }
    __syncthreads();
    int warp = tid>>5, lane = tid&31;
    int gw = blockIdx.x*8+warp, nw = gridDim.x*8;
    for(int n=gw; n<Nn; n+=nw){
        float* st = stage[warp];
        for(int i=lane;i<64;i+=32)  st[i]    = ns[n*64+i];
        for(int i=lane;i<192;i+=32) st[64+i] = nv[n*192+i];
        __syncwarp();
        int sp = spec[n];
        const float* wss = Wss + sp*8192;   // [64][128]
        const float* wsv = Wsv + sp*4096;   // [64][64]
        float asu0=0.f, asu1=0.f;
        float avu[2][3]={{0,0,0},{0,0,0}};
        float aks[4]={0,0,0,0};
        float akv[2][3]={{0,0,0},{0,0,0}};
        for(int c=0;c<64;c++){
            float s  = st[c];
            float v0 = st[64+3*c], v1 = st[64+3*c+1], v2 = st[64+3*c+2];
            float w0 = sWus[c*64+lane], w1 = sWus[c*64+lane+32];
            asu0 += s*w0; asu1 += s*w1;
            float u0 = sWuv[c*64+lane], u1 = sWuv[c*64+lane+32];
            avu[0][0]+=v0*u0; avu[0][1]+=v1*u0; avu[0][2]+=v2*u0;
            avu[1][0]+=v0*u1; avu[1][1]+=v1*u1; avu[1][2]+=v2*u1;
            #pragma unroll
            for(int j=0;j<4;j++) aks[j] += s*wss[c*128+lane+32*j];
            float k0 = wsv[c*64+lane], k1 = wsv[c*64+lane+32];
            akv[0][0]+=v0*k0; akv[0][1]+=v1*k0; akv[0][2]+=v2*k0;
            akv[1][0]+=v0*k1; akv[1][1]+=v1*k1; akv[1][2]+=v2*k1;
        }
        const float sc = 0.125f;   // 1/sqrt(64)
        g_s_up[n*64+lane]    = asu0*sc;
        g_s_up[n*64+lane+32] = asu1*sc;
        #pragma unroll
        for(int i=0;i<3;i++){
            g_v_up[n*192+3*lane+i]      = avu[0][i]*sc;
            g_v_up[n*192+3*(lane+32)+i] = avu[1][i]*sc;
        }
        #pragma unroll
        for(int j=0;j<4;j++) g_skip_s[n*128+lane+32*j] = aks[j]*sc;
        #pragma unroll
        for(int j=0;j<2;j++)
            #pragma unroll
            for(int i=0;i<3;i++)
                g_skip_v[n*192+3*(lane+32*j)+i] = akv[j][i]*sc;
        __syncwarp();
    }
}

// ---------------- K2: radial MLP -> g_mix [E,320]  (f32x2, 32-edge tiles) ---
// smem floats: W1 512 | W2 4096 | W3 20480 | rad 256 | h1 32*65 | h2 32*65
#define MLP_SMEM_FLOATS (512+4096+20480+256+2080+2080)
__global__ __launch_bounds__(256) void k_mlp(
    const float* __restrict__ vecs,
    const float* __restrict__ W1, const float* __restrict__ W2,
    const float* __restrict__ W3)
{
    extern __shared__ float sm[];
    float* sW1 = sm;
    float* sW2 = sm+512;
    float* sW3 = sm+4608;
    float* sRad= sm+25088;
    float* sH1 = sm+25344;
    float* sH2 = sm+27424;
    int tid = threadIdx.x;
    for(int i=tid;i<512;i+=256)   sW1[i]=W1[i];
    for(int i=tid;i<4096;i+=256)  sW2[i]=W2[i];
    for(int i=tid;i<20480;i+=256) sW3[i]=W3[i];
    __syncthreads();

    const float PI = 3.14159265358979f;
    const float SQRT2 = 1.41421356237f;
    int e_loc = tid>>3, oo = tid&7;      // 32 edges x 8 threads

    for(int tile=blockIdx.x; tile<Ne/32; tile+=gridDim.x){
        int ebase = tile*32;
        // ---- radial embedding (32 threads, one edge each)
        if(tid < 32){
            int e = ebase + tid;
            float x = vecs[3*e], y = vecs[3*e+1], z = vecs[3*e+2];
            float r = sqrtf(x*x+y*y+z*z);
            float r2 = r*r, r3 = r2*r;
            float x6 = r3*r3;
            float env = 1.f - 28.f*x6 + 48.f*x6*r - 21.f*x6*r2;
            if(r >= 1.f) env = 0.f;
            float coef = SQRT2*env/r;
            float pr = PI*r;
            #pragma unroll
            for(int k=0;k<8;k++) sRad[tid*8+k] = coef*sinf((float)(k+1)*pr);
        }
        __syncthreads();
        // ---- h1 = swish(rad @ W1 / sqrt(8))  [32 x 64]
        {
            float acc[8];
            #pragma unroll
            for(int j=0;j<8;j++) acc[j]=0.f;
            #pragma unroll
            for(int k=0;k<8;k++){
                float r = sRad[e_loc*8+k];
                #pragma unroll
                for(int j=0;j<8;j++) acc[j] += r*sW1[k*64+oo*8+j];
            }
            #pragma unroll
            for(int j=0;j<8;j++) sH1[e_loc*65+oo*8+j] = sw(acc[j]*0.35355339059f);
        }
        __syncthreads();
        // ---- h2 = swish(h1 @ W2 / 8)  [32 x 64], f32x2
        {
            u64t acc[4] = {0,0,0,0};
            for(int k=0;k<64;k++){
                float h = sH1[e_loc*65+k];
                u64t hp = pk(h,h);
                const float4 w0 = *reinterpret_cast<const float4*>(&sW2[k*64+oo*8]);
                const float4 w1 = *reinterpret_cast<const float4*>(&sW2[k*64+oo*8+4]);
                fma2(acc[0],hp,pk(w0.x,w0.y)); fma2(acc[1],hp,pk(w0.z,w0.w));
                fma2(acc[2],hp,pk(w1.x,w1.y)); fma2(acc[3],hp,pk(w1.z,w1.w));
            }
            #pragma unroll
            for(int p=0;p<4;p++){
                float2 v = up2(acc[p]);
                sH2[e_loc*65+oo*8+2*p]   = sw(v.x*0.125f);
                sH2[e_loc*65+oo*8+2*p+1] = sw(v.y*0.125f);
            }
        }
        __syncthreads();
        // ---- mix = h2 @ W3 / 8, fold scatter 1/4  [32 x 320], f32x2 -> g_mix
        {
            u64t acc[20];
            #pragma unroll
            for(int j=0;j<20;j++) acc[j]=0ULL;
            for(int k=0;k<64;k++){
                float h = sH2[e_loc*65+k];
                u64t hp = pk(h,h);
                #pragma unroll
                for(int jj=0;jj<10;jj++){
                    const float4 w = *reinterpret_cast<const float4*>(
                        &sW3[k*320 + oo*4 + 32*jj]);
                    fma2(acc[2*jj],   hp, pk(w.x,w.y));
                    fma2(acc[2*jj+1], hp, pk(w.z,w.w));
                }
            }
            size_t base = (size_t)(ebase+e_loc)*320;
            #pragma unroll
            for(int jj=0;jj<10;jj++){
                float2 a = up2(acc[2*jj]), b = up2(acc[2*jj+1]);
                float4 r;
                r.x=a.x*0.03125f; r.y=a.y*0.03125f;
                r.z=b.x*0.03125f; r.w=b.y*0.03125f;
                *reinterpret_cast<float4*>(&g_mix[base+oo*4+32*jj]) = r;
            }
        }
        __syncthreads();
    }
}

// ---------------- K3: edge message + atomic scatter -------------------------
__global__ __launch_bounds__(256) void k_edge(
    const float* __restrict__ vecs,
    const int* __restrict__ send, const int* __restrict__ recv)
{
    __shared__ float smsg[8][704];
    int warp = threadIdx.x>>5, lane = threadIdx.x&31;
    int gw = blockIdx.x*8+warp, nw = gridDim.x*8;
    float* msg = smsg[warp];
    const float SQRT3 = 1.73205080757f;
    const float CRS   = 1.22474487139f;  // sqrt(3)/sqrt(2)
    for(int e=gw; e<Ne; e+=nw){
        float vx=vecs[3*e], vy=vecs[3*e+1], vz=vecs[3*e+2];
        float invr = rsqrtf(vx*vx+vy*vy+vz*vz);
        float ux=vx*invr, uy=vy*invr, uz=vz*invr;
        int s = send[e], r = recv[e];
        const float* su = g_s_up + s*64;
        const float* vu = g_v_up + (size_t)s*192;
        const float* mx = g_mix + (size_t)e*320;
        #pragma unroll
        for(int t=0;t<2;t++){
            int c = lane + 32*t;
            float ms = su[c];
            float m0 = vu[3*c], m1 = vu[3*c+1], m2 = vu[3*c+2];
            float x0 = mx[c], x1 = mx[64+c], x2 = mx[128+c];
            float x3 = mx[192+c], x4 = mx[256+c];
            msg[c]    = ms*x0;
            msg[64+c] = (m0*ux+m1*uy+m2*uz)*x1;
            msg[128+0*192+c] = m0*x2;
            msg[128+1*192+c] = m1*x2;
            msg[128+2*192+c] = m2*x2;
            float s3 = ms*SQRT3*x3;
            msg[128+0*192+64+c] = s3*ux;
            msg[128+1*192+64+c] = s3*uy;
            msg[128+2*192+64+c] = s3*uz;
            float c4 = CRS*x4;
            msg[128+0*192+128+c] = (m1*uz-m2*uy)*c4;
            msg[128+1*192+128+c] = (m2*ux-m0*uz)*c4;
            msg[128+2*192+128+c] = (m0*uy-m1*ux)*c4;
        }
        __syncwarp();
        float* aggs = g_agg_s + (size_t)r*128;
        float* aggv = g_agg_v + (size_t)r*576;
        for(int g=lane; g<176; g+=32){
            const float4 v = *reinterpret_cast<const float4*>(&msg[4*g]);
            float* dst = (g<32) ? (aggs + 4*g) : (aggv + 4*g - 128);
            red4(dst, v.x, v.y, v.z, v.w);
        }
        __syncwarp();
    }
}

// ---------------- K4: down-projection + skip + gate -> output ---------------
// 512 threads, 16 warps. smem: Wds 16384 | Wdv 12288 | stage 16*960
#define OUT_SMEM_FLOATS (16384+12288+16*960)
__global__ __launch_bounds__(512) void k_node_out(
    const float* __restrict__ Wds, const float* __restrict__ Wdv,
    float* __restrict__ out)
{
    extern __shared__ float sm[];
    float* sWds = sm;
    float* sWdv = sm+16384;
    float* stage= sm+28672;
    int tid = threadIdx.x;
    for(int i=tid;i<16384;i+=512) sWds[i]=Wds[i];
    for(int i=tid;i<12288;i+=512) sWdv[i]=Wdv[i];
    __syncthreads();
    int warp = tid>>5, lane = tid&31;
    const float ISNS = 0.08838834765f;  // 1/sqrt(128)
    const float ISNV = 0.07216878365f;  // 1/sqrt(192)
    float* st   = stage + warp*960;
    float* st_s = st;          // 128
    float* st_v = st+128;      // 768  ([c][4] padded)
    float* st_g = st+896;      // 64 gates
    for(int n = blockIdx.x*16+warp; n<Nn; n += gridDim.x*16){
        for(int i=lane;i<128;i+=32) st_s[i] = g_agg_s[n*128+i];
        #pragma unroll
        for(int i3=0;i3<3;i3++)
            for(int c=lane;c<192;c+=32)
                st_v[c*4+i3] = g_agg_v[(size_t)n*576 + i3*192 + c];
        __syncwarp();
        // ---- out_s = agg_s @ Wds : thread owns channels lane*4 + {0..3}
        u64t a01=0ULL, a23=0ULL;
        for(int c=0;c<128;c++){
            float a = st_s[c];
            u64t ap = pk(a,a);
            const float4 w = *reinterpret_cast<const float4*>(&sWds[c*128+lane*4]);
            fma2(a01, ap, pk(w.x,w.y));
            fma2(a23, ap, pk(w.z,w.w));
        }
        // ---- out_v = agg_v @ Wdv : thread owns channels lane*2 + {0,1}
        u64t av[3]={0ULL,0ULL,0ULL};
        for(int c=0;c<192;c++){
            const float4 a = *reinterpret_cast<const float4*>(&st_v[c*4]);
            const float2 w = *reinterpret_cast<const float2*>(&sWdv[c*64+lane*2]);
            u64t wp = pk(w.x,w.y);
            fma2(av[0], pk(a.x,a.x), wp);
            fma2(av[1], pk(a.y,a.y), wp);
            fma2(av[2], pk(a.z,a.z), wp);
        }
        // ---- finalize scalars
        float2 s01 = up2(a01), s23 = up2(a23);
        float os[4] = {s01.x, s01.y, s23.x, s23.y};
        const float4 sk = *reinterpret_cast<const float4*>(&g_skip_s[n*128+lane*4]);
        os[0]=os[0]*ISNS+sk.x; os[1]=os[1]*ISNS+sk.y;
        os[2]=os[2]*ISNS+sk.z; os[3]=os[3]*ISNS+sk.w;
        if(lane>=16){
            #pragma unroll
            for(int j=0;j<4;j++) st_g[(lane-16)*4+j] = sw(os[j]);
        }
        // ---- finalize vectors
        float ov[3][2];
        #pragma unroll
        for(int i3=0;i3<3;i3++){
            float2 t = up2(av[i3]);
            ov[i3][0]=t.x; ov[i3][1]=t.y;
        }
        int o0 = lane*2;
        #pragma unroll
        for(int j=0;j<2;j++)
            #pragma unroll
            for(int i3=0;i3<3;i3++)
                ov[i3][j] = ov[i3][j]*ISNV + g_skip_v[(size_t)n*192+3*(o0+j)+i3];
        __syncwarp();
        float* o = out + (size_t)n*256;
        if(lane<16){
            float4 r;
            r.x=sw(os[0]); r.y=sw(os[1]); r.z=sw(os[2]); r.w=sw(os[3]);
            *reinterpret_cast<float4*>(&o[lane*4]) = r;
        }
        #pragma unroll
        for(int j=0;j<2;j++){
            float g = st_g[o0+j];
            #pragma unroll
            for(int i3=0;i3<3;i3++)
                o[64+3*(o0+j)+i3] = ov[i3][j]*g;
        }
        __syncwarp();
    }
}

// ---------------- launch ----------------------------------------------------
extern "C" void kernel_launch(void* const* d_in, const int* in_sizes, int n_in,
                              void* d_out, int out_size)
{
    const float* vectors  = (const float*)d_in[0];
    const float* node_s   = (const float*)d_in[1];
    const float* node_v   = (const float*)d_in[2];
    const int*   spec     = (const int*)  d_in[3];
    const int*   senders  = (const int*)  d_in[4];
    const int*   receivers= (const int*)  d_in[5];
    const float* Wss      = (const float*)d_in[6];
    const float* Wsv      = (const float*)d_in[7];
    const float* Wus      = (const float*)d_in[8];
    const float* Wuv      = (const float*)d_in[9];
    const float* W1       = (const float*)d_in[10];
    const float* W2       = (const float*)d_in[11];
    const float* W3       = (const float*)d_in[12];
    const float* Wds      = (const float*)d_in[13];
    const float* Wdv      = (const float*)d_in[14];
    float* out = (float*)d_out;

    void *pa, *pv;
    cudaGetSymbolAddress(&pa, g_agg_s);
    cudaGetSymbolAddress(&pv, g_agg_v);
    cudaMemsetAsync(pa, 0, (size_t)Nn*128*sizeof(float));
    cudaMemsetAsync(pv, 0, (size_t)Nn*576*sizeof(float));

    cudaFuncSetAttribute(k_mlp, cudaFuncAttributeMaxDynamicSharedMemorySize,
                         MLP_SMEM_FLOATS*4);
    cudaFuncSetAttribute(k_node_out, cudaFuncAttributeMaxDynamicSharedMemorySize,
                         OUT_SMEM_FLOATS*4);

    k_node_prep<<<1250, 256>>>(node_s, node_v, spec, Wss, Wsv, Wus, Wuv);
    k_mlp<<<148, 256, MLP_SMEM_FLOATS*4>>>(vectors, W1, W2, W3);
    k_edge<<<625, 256>>>(vectors, senders, receivers);
    k_node_out<<<148, 512, OUT_SMEM_FLOATS*4>>>(Wds, Wdv, out);
}

// round 5
// speedup vs baseline: 1.9196x; 1.9196x over previous
#include <cuda_runtime.h>
#include <math.h>

#define Nn 10000
#define Ne 160000

// ---------------- scratch (device globals; no allocation allowed) ----------
__device__ float g_s_up [Nn*64];
__device__ float g_v_up [Nn*192];        // [n][c*3+i]
__device__ float g_skip_s[Nn*128];
__device__ float g_skip_v[Nn*192];       // [n][c*3+i]
__device__ float g_agg_s[Nn*128];
__device__ float g_agg_v[Nn*576];        // [n][i][o] : i<3, o<192
__device__ float g_mix  [(size_t)Ne*320];

__device__ __forceinline__ float sw(float x){ return x/(1.f+__expf(-x)); }

__device__ __forceinline__ void red4(float* p, float a, float b, float c, float d){
    asm volatile("red.global.add.v4.f32 [%0], {%1,%2,%3,%4};"
                 :: "l"(p), "f"(a), "f"(b), "f"(c), "f"(d) : "memory");
}

// ---- packed f32x2 helpers (sm_100+) ----
typedef unsigned long long u64t;
__device__ __forceinline__ u64t pk(float lo, float hi){
    u64t r; asm("mov.b64 %0, {%1,%2};" : "=l"(r) : "f"(lo), "f"(hi)); return r;
}
__device__ __forceinline__ void fma2(u64t &d, u64t a, u64t b){
    asm("fma.rn.f32x2 %0, %1, %2, %0;" : "+l"(d) : "l"(a), "l"(b));
}
__device__ __forceinline__ float2 up2(u64t v){
    float2 r; asm("mov.b64 {%0,%1}, %2;" : "=f"(r.x), "=f"(r.y) : "l"(v)); return r;
}

// ---------------- K1: node prep (s_up, v_up, skip_s, skip_v) ---------------
__global__ __launch_bounds__(256) void k_node_prep(
    const float* __restrict__ ns, const float* __restrict__ nv,
    const int*   __restrict__ spec,
    const float* __restrict__ Wss, const float* __restrict__ Wsv,
    const float* __restrict__ Wus, const float* __restrict__ Wuv)
{
    __shared__ float sWus[4096], sWuv[4096];
    __shared__ float stage[8][256];
    int tid = threadIdx.x;
    for(int i=tid;i<4096;i+=256){ sWus[i]=Wus[i]; sWuv[i]=Wuv[i]; }
    __syncthreads();
    int warp = tid>>5, lane = tid&31;
    int gw = blockIdx.x*8+warp, nw = gridDim.x*8;
    for(int n=gw; n<Nn; n+=nw){
        float* st = stage[warp];
        for(int i=lane;i<64;i+=32)  st[i]    = ns[n*64+i];
        for(int i=lane;i<192;i+=32) st[64+i] = nv[n*192+i];
        __syncwarp();
        int sp = spec[n];
        const float* wss = Wss + sp*8192;   // [64][128]
        const float* wsv = Wsv + sp*4096;   // [64][64]
        float asu0=0.f, asu1=0.f;
        float avu[2][3]={{0,0,0},{0,0,0}};
        float aks[4]={0,0,0,0};
        float akv[2][3]={{0,0,0},{0,0,0}};
        for(int c=0;c<64;c++){
            float s  = st[c];
            float v0 = st[64+3*c], v1 = st[64+3*c+1], v2 = st[64+3*c+2];
            float w0 = sWus[c*64+lane], w1 = sWus[c*64+lane+32];
            asu0 += s*w0; asu1 += s*w1;
            float u0 = sWuv[c*64+lane], u1 = sWuv[c*64+lane+32];
            avu[0][0]+=v0*u0; avu[0][1]+=v1*u0; avu[0][2]+=v2*u0;
            avu[1][0]+=v0*u1; avu[1][1]+=v1*u1; avu[1][2]+=v2*u1;
            #pragma unroll
            for(int j=0;j<4;j++) aks[j] += s*wss[c*128+lane+32*j];
            float k0 = wsv[c*64+lane], k1 = wsv[c*64+lane+32];
            akv[0][0]+=v0*k0; akv[0][1]+=v1*k0; akv[0][2]+=v2*k0;
            akv[1][0]+=v0*k1; akv[1][1]+=v1*k1; akv[1][2]+=v2*k1;
        }
        const float sc = 0.125f;   // 1/sqrt(64)
        g_s_up[n*64+lane]    = asu0*sc;
        g_s_up[n*64+lane+32] = asu1*sc;
        #pragma unroll
        for(int i=0;i<3;i++){
            g_v_up[n*192+3*lane+i]      = avu[0][i]*sc;
            g_v_up[n*192+3*(lane+32)+i] = avu[1][i]*sc;
        }
        #pragma unroll
        for(int j=0;j<4;j++) g_skip_s[n*128+lane+32*j] = aks[j]*sc;
        #pragma unroll
        for(int j=0;j<2;j++)
            #pragma unroll
            for(int i=0;i<3;i++)
                g_skip_v[n*192+3*(lane+32*j)+i] = akv[j][i]*sc;
        __syncwarp();
    }
}

// ---------------- K2: radial MLP -> g_mix [E,320] -------------------------
// 64-edge tiles, f32x2 FMA, edge-amortized weight loads, transposed H bufs.
// smem floats: W1 512 | W2 4096 | W3 20480 | radT 512 | H1T 64*68 | H2T 64*68
#define MLP_SMEM_FLOATS (512+4096+20480+512+4352+4352)
__global__ __launch_bounds__(256) void k_mlp(
    const float* __restrict__ vecs,
    const float* __restrict__ W1, const float* __restrict__ W2,
    const float* __restrict__ W3)
{
    extern __shared__ float sm[];
    float* sW1  = sm;
    float* sW2  = sm+512;
    float* sW3  = sm+4608;
    float* sRadT= sm+25088;      // [k][64]
    float* sH1T = sm+25600;      // [k][68]
    float* sH2T = sm+25600+4352; // [k][68]
    int tid = threadIdx.x;
    for(int i=tid;i<512;i+=256)   sW1[i]=W1[i];
    for(int i=tid;i<4096;i+=256)  sW2[i]=W2[i];
    for(int i=tid;i<20480;i+=256) sW3[i]=W3[i];
    __syncthreads();

    const float PI = 3.14159265358979f;
    const float SQRT2 = 1.41421356237f;

    // stage mappings
    int e1  = tid&63,  og1 = tid>>6;          // h1: edge, out-group(16)
    int ebl = (tid&15)*4, obl = (tid>>4)*4;   // h2: 4 edges x 4 outs
    int eg  = tid>>5,  ot  = tid&31;          // mix: 8 edges x 10 outs (pairs)

    for(int tile=blockIdx.x; tile<Ne/64; tile+=gridDim.x){
        int ebase = tile*64;
        // ---- radial embedding -> sRadT[k][e]
        if(tid < 64){
            int e = ebase + tid;
            float x = vecs[3*e], y = vecs[3*e+1], z = vecs[3*e+2];
            float r = sqrtf(x*x+y*y+z*z);
            float r2 = r*r, r3 = r2*r;
            float x6 = r3*r3;
            float env = 1.f - 28.f*x6 + 48.f*x6*r - 21.f*x6*r2;
            if(r >= 1.f) env = 0.f;
            float coef = SQRT2*env/r;
            float pr = PI*r;
            #pragma unroll
            for(int k=0;k<8;k++) sRadT[k*64+tid] = coef*sinf((float)(k+1)*pr);
        }
        __syncthreads();
        // ---- h1 = swish(rad @ W1 / sqrt(8)) -> sH1T[o][e]
        {
            u64t a[8];
            #pragma unroll
            for(int j=0;j<8;j++) a[j]=0ULL;
            #pragma unroll
            for(int k=0;k<8;k++){
                float r = sRadT[k*64+e1];
                u64t rp = pk(r,r);
                #pragma unroll
                for(int j=0;j<8;j++){
                    u64t w = *(const u64t*)&sW1[k*64 + og1*16 + 2*j];
                    fma2(a[j], rp, w);
                }
            }
            #pragma unroll
            for(int j=0;j<8;j++){
                float2 v = up2(a[j]);
                sH1T[(og1*16+2*j)*68 + e1]   = sw(v.x*0.35355339059f);
                sH1T[(og1*16+2*j+1)*68 + e1] = sw(v.y*0.35355339059f);
            }
        }
        __syncthreads();
        // ---- h2 = swish(h1 @ W2 / 8) -> sH2T[o][e]   (4 edges x 4 outs)
        {
            u64t b[4][2];
            #pragma unroll
            for(int i=0;i<4;i++){ b[i][0]=0ULL; b[i][1]=0ULL; }
            for(int k=0;k<64;k++){
                const float4 h = *(const float4*)&sH1T[k*68 + ebl];
                const ulonglong2 w = *(const ulonglong2*)&sW2[k*64 + obl];
                u64t h0=pk(h.x,h.x), h1=pk(h.y,h.y), h2v=pk(h.z,h.z), h3=pk(h.w,h.w);
                fma2(b[0][0],h0,w.x); fma2(b[0][1],h0,w.y);
                fma2(b[1][0],h1,w.x); fma2(b[1][1],h1,w.y);
                fma2(b[2][0],h2v,w.x); fma2(b[2][1],h2v,w.y);
                fma2(b[3][0],h3,w.x); fma2(b[3][1],h3,w.y);
            }
            #pragma unroll
            for(int i=0;i<4;i++){
                #pragma unroll
                for(int p=0;p<2;p++){
                    float2 v = up2(b[i][p]);
                    sH2T[(obl+2*p)*68 + ebl+i]   = sw(v.x*0.125f);
                    sH2T[(obl+2*p+1)*68 + ebl+i] = sw(v.y*0.125f);
                }
            }
        }
        __syncthreads();
        // ---- mix = h2 @ W3 * (1/8)*(1/4) -> g_mix   (8 edges x 10 outs)
        {
            u64t m[8][5];
            #pragma unroll
            for(int i=0;i<8;i++)
                #pragma unroll
                for(int j=0;j<5;j++) m[i][j]=0ULL;
            for(int k=0;k<64;k++){
                const float4 ha = *(const float4*)&sH2T[k*68 + eg*8];
                const float4 hb = *(const float4*)&sH2T[k*68 + eg*8 + 4];
                u64t wj[5];
                #pragma unroll
                for(int j=0;j<5;j++)
                    wj[j] = *(const u64t*)&sW3[k*320 + 2*ot + 64*j];
                u64t hp;
                hp=pk(ha.x,ha.x);
                #pragma unroll
                for(int j=0;j<5;j++) fma2(m[0][j],hp,wj[j]);
                hp=pk(ha.y,ha.y);
                #pragma unroll
                for(int j=0;j<5;j++) fma2(m[1][j],hp,wj[j]);
                hp=pk(ha.z,ha.z);
                #pragma unroll
                for(int j=0;j<5;j++) fma2(m[2][j],hp,wj[j]);
                hp=pk(ha.w,ha.w);
                #pragma unroll
                for(int j=0;j<5;j++) fma2(m[3][j],hp,wj[j]);
                hp=pk(hb.x,hb.x);
                #pragma unroll
                for(int j=0;j<5;j++) fma2(m[4][j],hp,wj[j]);
                hp=pk(hb.y,hb.y);
                #pragma unroll
                for(int j=0;j<5;j++) fma2(m[5][j],hp,wj[j]);
                hp=pk(hb.z,hb.z);
                #pragma unroll
                for(int j=0;j<5;j++) fma2(m[6][j],hp,wj[j]);
                hp=pk(hb.w,hb.w);
                #pragma unroll
                for(int j=0;j<5;j++) fma2(m[7][j],hp,wj[j]);
            }
            #pragma unroll
            for(int i=0;i<8;i++){
                size_t base = (size_t)(ebase + eg*8 + i)*320;
                #pragma unroll
                for(int j=0;j<5;j++){
                    float2 v = up2(m[i][j]);
                    float2 r; r.x=v.x*0.03125f; r.y=v.y*0.03125f;
                    *reinterpret_cast<float2*>(&g_mix[base + 2*ot + 64*j]) = r;
                }
            }
        }
        __syncthreads();
    }
}

// ---------------- K3: edge message + atomic scatter -------------------------
__global__ __launch_bounds__(256) void k_edge(
    const float* __restrict__ vecs,
    const int* __restrict__ send, const int* __restrict__ recv)
{
    __shared__ float smsg[8][704];
    int warp = threadIdx.x>>5, lane = threadIdx.x&31;
    int gw = blockIdx.x*8+warp, nw = gridDim.x*8;
    float* msg = smsg[warp];
    const float SQRT3 = 1.73205080757f;
    const float CRS   = 1.22474487139f;  // sqrt(3)/sqrt(2)
    for(int e=gw; e<Ne; e+=nw){
        float vx=vecs[3*e], vy=vecs[3*e+1], vz=vecs[3*e+2];
        float invr = rsqrtf(vx*vx+vy*vy+vz*vz);
        float ux=vx*invr, uy=vy*invr, uz=vz*invr;
        int s = send[e], r = recv[e];
        const float* su = g_s_up + s*64;
        const float* vu = g_v_up + (size_t)s*192;
        const float* mx = g_mix + (size_t)e*320;
        #pragma unroll
        for(int t=0;t<2;t++){
            int c = lane + 32*t;
            float ms = su[c];
            float m0 = vu[3*c], m1 = vu[3*c+1], m2 = vu[3*c+2];
            float x0 = mx[c], x1 = mx[64+c], x2 = mx[128+c];
            float x3 = mx[192+c], x4 = mx[256+c];
            msg[c]    = ms*x0;
            msg[64+c] = (m0*ux+m1*uy+m2*uz)*x1;
            msg[128+0*192+c] = m0*x2;
            msg[128+1*192+c] = m1*x2;
            msg[128+2*192+c] = m2*x2;
            float s3 = ms*SQRT3*x3;
            msg[128+0*192+64+c] = s3*ux;
            msg[128+1*192+64+c] = s3*uy;
            msg[128+2*192+64+c] = s3*uz;
            float c4 = CRS*x4;
            msg[128+0*192+128+c] = (m1*uz-m2*uy)*c4;
            msg[128+1*192+128+c] = (m2*ux-m0*uz)*c4;
            msg[128+2*192+128+c] = (m0*uy-m1*ux)*c4;
        }
        __syncwarp();
        float* aggs = g_agg_s + (size_t)r*128;
        float* aggv = g_agg_v + (size_t)r*576;
        for(int g=lane; g<176; g+=32){
            const float4 v = *reinterpret_cast<const float4*>(&msg[4*g]);
            float* dst = (g<32) ? (aggs + 4*g) : (aggv + 4*g - 128);
            red4(dst, v.x, v.y, v.z, v.w);
        }
        __syncwarp();
    }
}

// ---------------- K4: down-projection + skip + gate -> output (R2 version) --
// smem floats: Wds 16384 | Wdv 12288 | stage 8*704
#define OUT_SMEM_FLOATS (16384+12288+5632)
__global__ __launch_bounds__(256) void k_node_out(
    const float* __restrict__ Wds, const float* __restrict__ Wdv,
    float* __restrict__ out)
{
    extern __shared__ float sm[];
    float* sWds = sm;
    float* sWdv = sm+16384;
    float* sAgg = sm+16384+12288;
    int tid = threadIdx.x;
    for(int i=tid;i<16384;i+=256) sWds[i]=Wds[i];
    for(int i=tid;i<12288;i+=256) sWdv[i]=Wdv[i];
    __syncthreads();
    int warp = tid>>5, lane = tid&31;
    int gw = blockIdx.x*8+warp, nw = gridDim.x*8;
    const float ISNS = 0.08838834765f;  // 1/sqrt(128)
    const float ISNV = 0.07216878365f;  // 1/sqrt(192)
    float* st = sAgg + warp*704;
    for(int n=gw; n<Nn; n+=nw){
        for(int i=lane;i<128;i+=32) st[i]     = g_agg_s[n*128+i];
        for(int i=lane;i<576;i+=32) st[128+i] = g_agg_v[(size_t)n*576+i];
        __syncwarp();
        float os[4]={0,0,0,0};
        for(int c=0;c<128;c++){
            float a = st[c];
            #pragma unroll
            for(int j=0;j<4;j++) os[j] += a*sWds[c*128+lane+32*j];
        }
        float ov[2][3]={{0,0,0},{0,0,0}};
        for(int c=0;c<192;c++){
            float a0 = st[128+c], a1 = st[128+192+c], a2 = st[128+384+c];
            #pragma unroll
            for(int j=0;j<2;j++){
                float w = sWdv[c*64+lane+32*j];
                ov[j][0]+=a0*w; ov[j][1]+=a1*w; ov[j][2]+=a2*w;
            }
        }
        #pragma unroll
        for(int j=0;j<4;j++) os[j] = os[j]*ISNS + g_skip_s[n*128+lane+32*j];
        #pragma unroll
        for(int j=0;j<2;j++)
            #pragma unroll
            for(int i=0;i<3;i++)
                ov[j][i] = ov[j][i]*ISNV + g_skip_v[(size_t)n*192+3*(lane+32*j)+i];
        float g0 = sw(os[2]), g1 = sw(os[3]);
        float* o = out + (size_t)n*256;
        o[lane]    = sw(os[0]);
        o[lane+32] = sw(os[1]);
        #pragma unroll
        for(int i=0;i<3;i++){
            o[64+3*lane+i]      = ov[0][i]*g0;
            o[64+3*(lane+32)+i] = ov[1][i]*g1;
        }
        __syncwarp();
    }
}

// ---------------- launch ----------------------------------------------------
extern "C" void kernel_launch(void* const* d_in, const int* in_sizes, int n_in,
                              void* d_out, int out_size)
{
    const float* vectors  = (const float*)d_in[0];
    const float* node_s   = (const float*)d_in[1];
    const float* node_v   = (const float*)d_in[2];
    const int*   spec     = (const int*)  d_in[3];
    const int*   senders  = (const int*)  d_in[4];
    const int*   receivers= (const int*)  d_in[5];
    const float* Wss      = (const float*)d_in[6];
    const float* Wsv      = (const float*)d_in[7];
    const float* Wus      = (const float*)d_in[8];
    const float* Wuv      = (const float*)d_in[9];
    const float* W1       = (const float*)d_in[10];
    const float* W2       = (const float*)d_in[11];
    const float* W3       = (const float*)d_in[12];
    const float* Wds      = (const float*)d_in[13];
    const float* Wdv      = (const float*)d_in[14];
    float* out = (float*)d_out;

    void *pa, *pv;
    cudaGetSymbolAddress(&pa, g_agg_s);
    cudaGetSymbolAddress(&pv, g_agg_v);

    cudaFuncSetAttribute(k_mlp, cudaFuncAttributeMaxDynamicSharedMemorySize,
                         MLP_SMEM_FLOATS*4);
    cudaFuncSetAttribute(k_node_out, cudaFuncAttributeMaxDynamicSharedMemorySize,
                         OUT_SMEM_FLOATS*4);

    // fork-join: side stream runs memsets + node_prep concurrently with k_mlp
    cudaStream_t s2;
    cudaStreamCreateWithFlags(&s2, cudaStreamNonBlocking);
    cudaEvent_t evF, evJ;
    cudaEventCreateWithFlags(&evF, cudaEventDisableTiming);
    cudaEventCreateWithFlags(&evJ, cudaEventDisableTiming);

    cudaEventRecord(evF, 0);
    cudaStreamWaitEvent(s2, evF, 0);

    cudaMemsetAsync(pa, 0, (size_t)Nn*128*sizeof(float), s2);
    cudaMemsetAsync(pv, 0, (size_t)Nn*576*sizeof(float), s2);
    k_node_prep<<<1250, 256, 0, s2>>>(node_s, node_v, spec, Wss, Wsv, Wus, Wuv);
    cudaEventRecord(evJ, s2);

    k_mlp<<<148, 256, MLP_SMEM_FLOATS*4>>>(vectors, W1, W2, W3);

    cudaStreamWaitEvent(0, evJ, 0);
    k_edge<<<625, 256>>>(vectors, senders, receivers);
    k_node_out<<<148, 256, OUT_SMEM_FLOATS*4>>>(Wds, Wdv, out);

    cudaEventDestroy(evF);
    cudaEventDestroy(evJ);
    cudaStreamDestroy(s2);
}